// round 3
// baseline (speedup 1.0000x reference)
#include <cuda_runtime.h>

// LM pose solver: B=4096 batches, N=512 points, DOF=4 (tx,ty,tz,yaw).
// One CTA per batch. Point data staged in shared memory once; 11 fused
// residual+jacobian reduction passes (1 init + 10 LM iters). GN step reuses
// the carried jtj/grad (mathematically identical to recomputation at the
// accepted pose). Tiny 4x4 solves done in fp64 on thread 0.

#define NPTS    512
#define THREADS 128
#define PPT     (NPTS / THREADS)   // 4
#define NUM_ITER 10

__device__ __forceinline__ void solve4d(double A[4][4], double bv[4], double x[4]) {
    // Gaussian elimination with partial pivoting (4x4).
    for (int k = 0; k < 4; k++) {
        int p = k;
        double mx = fabs(A[k][k]);
        for (int i = k + 1; i < 4; i++) {
            double v = fabs(A[i][k]);
            if (v > mx) { mx = v; p = i; }
        }
        if (p != k) {
            for (int j = 0; j < 4; j++) { double t = A[k][j]; A[k][j] = A[p][j]; A[p][j] = t; }
            double t = bv[k]; bv[k] = bv[p]; bv[p] = t;
        }
        double inv = 1.0 / A[k][k];
        for (int i = k + 1; i < 4; i++) {
            double f = A[i][k] * inv;
            for (int j = k; j < 4; j++) A[i][j] -= f * A[k][j];
            bv[i] -= f * bv[k];
        }
    }
    for (int k = 3; k >= 0; k--) {
        double s = bv[k];
        for (int j = k + 1; j < 4; j++) s -= A[k][j] * x[j];
        x[k] = s / A[k][k];
    }
}

__global__ void __launch_bounds__(THREADS, 1) lm_kernel(
    const float* __restrict__ x3d,
    const float* __restrict__ x2d,
    const float* __restrict__ w2d,
    const float* __restrict__ pose_init,
    const float* __restrict__ cam,
    float* __restrict__ out,   // [4B pose | B cost | 4B pose_plus]
    int B)
{
    __shared__ float sX[NPTS], sY[NPTS], sZ[NPTS];
    __shared__ float sU[NPTS], sV[NPTS], sWU[NPTS], sWV[NPTS];
    __shared__ float red[4][15];
    __shared__ float bc[5];   // tx, ty, tz, cos(yaw), sin(yaw)

    const int b    = blockIdx.x;
    const int tid  = threadIdx.x;
    const int lane = tid & 31;
    const int wid  = tid >> 5;

    // ---- stage point data into smem (SoA) ----
    const float* __restrict__ xb = x3d + (size_t)b * NPTS * 3;
    const float* __restrict__ ub = x2d + (size_t)b * NPTS * 2;
    const float* __restrict__ wb = w2d + (size_t)b * NPTS * 2;
    for (int i = tid; i < NPTS; i += THREADS) {
        sX[i] = xb[3 * i + 0];
        sY[i] = xb[3 * i + 1];
        sZ[i] = xb[3 * i + 2];
    }
    for (int i = tid; i < NPTS; i += THREADS) {
        sU[i]  = ub[2 * i + 0];
        sV[i]  = ub[2 * i + 1];
        sWU[i] = wb[2 * i + 0];
        sWV[i] = wb[2 * i + 1];
    }

    float Kr[9];
#pragma unroll
    for (int k = 0; k < 9; k++) Kr[k] = cam[(size_t)b * 9 + k];

    // ---- thread-0 LM state ----
    float pose[4] = {0.f, 0.f, 0.f, 0.f};
    float pn[4]   = {0.f, 0.f, 0.f, 0.f};
    float stepv[4] = {0.f, 0.f, 0.f, 0.f};
    float jt[10], gr[4];
    float cst = 0.f, radius = 30.0f, dec = 2.0f;
#pragma unroll
    for (int k = 0; k < 10; k++) jt[k] = 0.f;
#pragma unroll
    for (int k = 0; k < 4; k++) gr[k] = 0.f;

    if (tid == 0) {
#pragma unroll
        for (int k = 0; k < 4; k++) pose[k] = pose_init[b * 4 + k];
        float sy, cy;
        sincosf(pose[3], &sy, &cy);
        bc[0] = pose[0]; bc[1] = pose[1]; bc[2] = pose[2];
        bc[3] = cy; bc[4] = sy;
    }
    __syncthreads();

    float acc[15];

    // One fused residual+jacobian reduction pass over the 512 points at the
    // pose currently broadcast in bc[]. Ends with red[][] populated and a
    // __syncthreads so thread 0 can gather.
    auto do_pass = [&]() {
        const float tx = bc[0], ty = bc[1], tz = bc[2];
        const float cc = bc[3], ss = bc[4];
#pragma unroll
        for (int k = 0; k < 15; k++) acc[k] = 0.f;
#pragma unroll
        for (int q = 0; q < PPT; q++) {
            const int i = tid + q * THREADS;
            const float X = sX[i], Y = sY[i], Z = sZ[i];
            const float p0 = fmaf(cc, X, fmaf(ss, Z, tx));
            const float p1 = Y + ty;
            const float p2 = fmaf(-ss, X, fmaf(cc, Z, tz));
            const float av = p2 - tz;          //  -s*X + c*Z
            const float bv = tx - p0;          // -(c*X + s*Z)
            const float ph0 = fmaf(Kr[0], p0, fmaf(Kr[1], p1, Kr[2] * p2));
            const float ph1 = fmaf(Kr[3], p0, fmaf(Kr[4], p1, Kr[5] * p2));
            const float ph2 = fmaf(Kr[6], p0, fmaf(Kr[7], p1, Kr[8] * p2));
            const float zc  = fmaxf(ph2, 0.1f);
            const float gz  = (ph2 > 0.1f) ? 1.f : ((ph2 == 0.1f) ? 0.5f : 0.f);
            const float invz = 1.0f / zc;
            const float u = ph0 * invz;
            const float v = ph1 * invz;
            const float wu = sWU[i], wv = sWV[i];
            const float ru = (u - sU[i]) * wu;
            const float rv = (v - sV[i]) * wv;
            // yaw columns of dph
            const float d0y = fmaf(Kr[0], av, Kr[2] * bv);
            const float d1y = fmaf(Kr[3], av, Kr[5] * bv);
            const float d2y = fmaf(Kr[6], av, Kr[8] * bv);
            const float su_ = wu * invz;
            const float sv_ = wv * invz;
            const float ug = u * gz;
            const float vg = v * gz;
            const float Ju0 = fmaf(-ug, Kr[6], Kr[0]) * su_;
            const float Ju1 = fmaf(-ug, Kr[7], Kr[1]) * su_;
            const float Ju2 = fmaf(-ug, Kr[8], Kr[2]) * su_;
            const float Ju3 = fmaf(-ug, d2y,  d0y ) * su_;
            const float Jv0 = fmaf(-vg, Kr[6], Kr[3]) * sv_;
            const float Jv1 = fmaf(-vg, Kr[7], Kr[4]) * sv_;
            const float Jv2 = fmaf(-vg, Kr[8], Kr[5]) * sv_;
            const float Jv3 = fmaf(-vg, d2y,  d1y ) * sv_;
            // jtj upper triangle
            acc[0] = fmaf(Ju0, Ju0, fmaf(Jv0, Jv0, acc[0]));
            acc[1] = fmaf(Ju0, Ju1, fmaf(Jv0, Jv1, acc[1]));
            acc[2] = fmaf(Ju0, Ju2, fmaf(Jv0, Jv2, acc[2]));
            acc[3] = fmaf(Ju0, Ju3, fmaf(Jv0, Jv3, acc[3]));
            acc[4] = fmaf(Ju1, Ju1, fmaf(Jv1, Jv1, acc[4]));
            acc[5] = fmaf(Ju1, Ju2, fmaf(Jv1, Jv2, acc[5]));
            acc[6] = fmaf(Ju1, Ju3, fmaf(Jv1, Jv3, acc[6]));
            acc[7] = fmaf(Ju2, Ju2, fmaf(Jv2, Jv2, acc[7]));
            acc[8] = fmaf(Ju2, Ju3, fmaf(Jv2, Jv3, acc[8]));
            acc[9] = fmaf(Ju3, Ju3, fmaf(Jv3, Jv3, acc[9]));
            // grad
            acc[10] = fmaf(Ju0, ru, fmaf(Jv0, rv, acc[10]));
            acc[11] = fmaf(Ju1, ru, fmaf(Jv1, rv, acc[11]));
            acc[12] = fmaf(Ju2, ru, fmaf(Jv2, rv, acc[12]));
            acc[13] = fmaf(Ju3, ru, fmaf(Jv3, rv, acc[13]));
            // 2*cost
            acc[14] = fmaf(ru, ru, fmaf(rv, rv, acc[14]));
        }
        // warp butterfly reduce
#pragma unroll
        for (int o = 16; o > 0; o >>= 1) {
#pragma unroll
            for (int k = 0; k < 15; k++)
                acc[k] += __shfl_xor_sync(0xffffffffu, acc[k], o);
        }
        if (lane == 0) {
#pragma unroll
            for (int k = 0; k < 15; k++) red[wid][k] = acc[k];
        }
        __syncthreads();
    };

    auto gather = [&](float t[15]) {
#pragma unroll
        for (int k = 0; k < 15; k++)
            t[k] = red[0][k] + red[1][k] + red[2][k] + red[3][k];
    };

    // ---- initial pass at pose_init ----
    do_pass();
    if (tid == 0) {
        float t[15];
        gather(t);
#pragma unroll
        for (int k = 0; k < 10; k++) jt[k] = t[k];
#pragma unroll
        for (int k = 0; k < 4; k++) gr[k] = t[10 + k];
        cst = 0.5f * t[14];
    }

    // ---- LM iterations ----
    for (int it = 0; it < NUM_ITER; it++) {
        if (tid == 0) {
            // jtj_lm = jtj + clip(diag)/radius on diagonal
            double A[4][4], bvec[4], xx[4];
            A[0][0] = jt[0]; A[0][1] = jt[1]; A[0][2] = jt[2]; A[0][3] = jt[3];
            A[1][0] = jt[1]; A[1][1] = jt[4]; A[1][2] = jt[5]; A[1][3] = jt[6];
            A[2][0] = jt[2]; A[2][1] = jt[5]; A[2][2] = jt[7]; A[2][3] = jt[8];
            A[3][0] = jt[3]; A[3][1] = jt[6]; A[3][2] = jt[8]; A[3][3] = jt[9];
            const float dg[4] = {jt[0], jt[4], jt[7], jt[9]};
#pragma unroll
            for (int i = 0; i < 4; i++) {
                float d = fminf(fmaxf(dg[i], 1e-6f), 1e32f);
                A[i][i] += (double)(d / radius);
                bvec[i] = (double)gr[i];
            }
            solve4d(A, bvec, xx);
#pragma unroll
            for (int i = 0; i < 4; i++) {
                stepv[i] = -(float)xx[i];
                pn[i] = pose[i] + stepv[i];
            }
            float sy, cy;
            sincosf(pn[3], &sy, &cy);
            bc[0] = pn[0]; bc[1] = pn[1]; bc[2] = pn[2];
            bc[3] = cy; bc[4] = sy;
        }
        __syncthreads();
        do_pass();
        if (tid == 0) {
            float t[15];
            gather(t);
            const float cn = 0.5f * t[14];
            // model_cost_change = -step . (grad + 0.5*jtj*step)
            float Hs0 = jt[0]*stepv[0] + jt[1]*stepv[1] + jt[2]*stepv[2] + jt[3]*stepv[3];
            float Hs1 = jt[1]*stepv[0] + jt[4]*stepv[1] + jt[5]*stepv[2] + jt[6]*stepv[3];
            float Hs2 = jt[2]*stepv[0] + jt[5]*stepv[1] + jt[7]*stepv[2] + jt[8]*stepv[3];
            float Hs3 = jt[3]*stepv[0] + jt[6]*stepv[1] + jt[8]*stepv[2] + jt[9]*stepv[3];
            float mcc = -(stepv[0] * (gr[0] + 0.5f * Hs0) +
                          stepv[1] * (gr[1] + 0.5f * Hs1) +
                          stepv[2] * (gr[2] + 0.5f * Hs2) +
                          stepv[3] * (gr[3] + 0.5f * Hs3));
            float rel = (cst - cn) / mcc;
            bool succ = (rel >= 1e-3f) && (mcc > 0.0f);
            if (succ) {
                float tmp = 2.f * rel - 1.f;
                float den = fmaxf(1.f - tmp * tmp * tmp, 1.f / 3.f);
                radius = fminf(radius / den, 1e16f);
                dec = 2.f;
#pragma unroll
                for (int k = 0; k < 10; k++) jt[k] = t[k];
#pragma unroll
                for (int k = 0; k < 4; k++) gr[k] = t[10 + k];
                cst = cn;
#pragma unroll
                for (int k = 0; k < 4; k++) pose[k] = pn[k];
            } else {
                radius = radius / dec;
                dec *= 2.f;
            }
        }
    }

    // ---- outputs + GN step (reuses carried jtj/grad: identical to
    //      recomputing J,r at the accepted pose) ----
    if (tid == 0) {
#pragma unroll
        for (int k = 0; k < 4; k++) out[b * 4 + k] = pose[k];
        out[4 * B + b] = cst;

        double A[4][4], bvec[4], xx[4];
        A[0][0] = jt[0]; A[0][1] = jt[1]; A[0][2] = jt[2]; A[0][3] = jt[3];
        A[1][0] = jt[1]; A[1][1] = jt[4]; A[1][2] = jt[5]; A[1][3] = jt[6];
        A[2][0] = jt[2]; A[2][1] = jt[5]; A[2][2] = jt[7]; A[2][3] = jt[8];
        A[3][0] = jt[3]; A[3][1] = jt[6]; A[3][2] = jt[8]; A[3][3] = jt[9];
#pragma unroll
        for (int i = 0; i < 4; i++) {
            A[i][i] += 1e-5;            // EPS * eye
            bvec[i] = (double)gr[i];
        }
        solve4d(A, bvec, xx);
#pragma unroll
        for (int k = 0; k < 4; k++)
            out[5 * B + b * 4 + k] = pose[k] - (float)xx[k];
    }
}

extern "C" void kernel_launch(void* const* d_in, const int* in_sizes, int n_in,
                              void* d_out, int out_size) {
    const float* x3d       = (const float*)d_in[0];
    const float* x2d       = (const float*)d_in[1];
    const float* w2d       = (const float*)d_in[2];
    const float* pose_init = (const float*)d_in[3];
    const float* cam_mats  = (const float*)d_in[4];
    const int B = in_sizes[3] / 4;
    float* out = (float*)d_out;
    lm_kernel<<<B, THREADS>>>(x3d, x2d, w2d, pose_init, cam_mats, out, B);
}

// round 7
// speedup vs baseline: 4.0700x; 4.0700x over previous
#include <cuda_runtime.h>

// LM pose solver: B=4096 batches, N=512 points, DOF=4 (tx,ty,tz,yaw).
// One 64-thread CTA per batch, 8 points/thread. Point data staged in smem
// once; 11 fused residual+jacobian reduction passes (1 init + 10 LM iters).
// All scalar LM bookkeeping (4x4 fp32 solve, trust-region update) is done
// redundantly by every thread (deterministic, divergence-free) so each pass
// needs exactly one __syncthreads (red[] is double-buffered). GN step reuses
// the carried jtj/grad (identical to recomputing at the accepted pose).

#define NPTS     512
#define THREADS  64
#define PPT      (NPTS / THREADS)   // 8
#define NUM_ITER 10

// fp32 Gaussian elimination, no pivoting (A is SPD + LM damping).
// Matches the reference's float32 jnp.linalg.solve to well under 1e-3.
__device__ __forceinline__ void solve4f(float A[4][4], float bv[4], float x[4]) {
#pragma unroll
    for (int k = 0; k < 4; k++) {
        const float inv = 1.0f / A[k][k];
#pragma unroll
        for (int i = 0; i < 4; i++) {
            if (i > k) {
                const float f = A[i][k] * inv;
#pragma unroll
                for (int j = 0; j < 4; j++)
                    if (j >= k) A[i][j] = fmaf(-f, A[k][j], A[i][j]);
                bv[i] = fmaf(-f, bv[k], bv[i]);
            }
        }
    }
#pragma unroll
    for (int k = 3; k >= 0; k--) {
        float s = bv[k];
#pragma unroll
        for (int j = 0; j < 4; j++)
            if (j > k) s = fmaf(-A[k][j], x[j], s);
        x[k] = s / A[k][k];
    }
}

__global__ void __launch_bounds__(THREADS, 12) lm_kernel(
    const float* __restrict__ x3d,
    const float* __restrict__ x2d,
    const float* __restrict__ w2d,
    const float* __restrict__ pose_init,
    const float* __restrict__ cam,
    float* __restrict__ out,   // [4B pose | B cost | 4B pose_plus]
    int B)
{
    __shared__ float sX[NPTS], sY[NPTS], sZ[NPTS];
    __shared__ float sU[NPTS], sV[NPTS], sWU[NPTS], sWV[NPTS];
    __shared__ float red[2][2][15];   // [buf][warp][acc]

    const int b    = blockIdx.x;
    const int tid  = threadIdx.x;
    const int lane = tid & 31;
    const int wid  = tid >> 5;

    // ---- stage point data into smem (SoA), one-time cost ----
    const float*  __restrict__ xb = x3d + (size_t)b * NPTS * 3;
    const float2* __restrict__ ub = (const float2*)(x2d + (size_t)b * NPTS * 2);
    const float2* __restrict__ wb = (const float2*)(w2d + (size_t)b * NPTS * 2);
    for (int i = tid; i < NPTS; i += THREADS) {
        sX[i] = xb[3 * i + 0];
        sY[i] = xb[3 * i + 1];
        sZ[i] = xb[3 * i + 2];
        const float2 u2 = ub[i];
        const float2 w2 = wb[i];
        sU[i] = u2.x;  sV[i] = u2.y;
        sWU[i] = w2.x; sWV[i] = w2.y;
    }

    float Kr[9];
#pragma unroll
    for (int k = 0; k < 9; k++) Kr[k] = cam[(size_t)b * 9 + k];

    // ---- per-thread (redundant, identical) LM state ----
    float pose[4];
#pragma unroll
    for (int k = 0; k < 4; k++) pose[k] = pose_init[b * 4 + k];
    float jt[10], gr[4];
    float cst = 0.f, radius = 30.0f, dec = 2.0f;

    float cy, sy;
    sincosf(pose[3], &sy, &cy);
    float tx = pose[0], ty = pose[1], tz = pose[2];

    __syncthreads();   // staging complete

    int buf = 0;
    float acc[15];

    // One fused residual+jacobian reduction pass at (tx,ty,tz,cy,sy).
    // On exit every thread holds the block-wide sums in acc[0..14].
    auto do_pass = [&]() {
#pragma unroll
        for (int k = 0; k < 15; k++) acc[k] = 0.f;
#pragma unroll 4
        for (int q = 0; q < PPT; q++) {
            const int i = tid + q * THREADS;
            const float X = sX[i], Y = sY[i], Z = sZ[i];
            const float p0 = fmaf(cy, X, fmaf(sy, Z, tx));
            const float p1 = Y + ty;
            const float p2 = fmaf(-sy, X, fmaf(cy, Z, tz));
            const float av = p2 - tz;          //  -s*X + c*Z
            const float bv = tx - p0;          // -(c*X + s*Z)
            const float ph0 = fmaf(Kr[0], p0, fmaf(Kr[1], p1, Kr[2] * p2));
            const float ph1 = fmaf(Kr[3], p0, fmaf(Kr[4], p1, Kr[5] * p2));
            const float ph2 = fmaf(Kr[6], p0, fmaf(Kr[7], p1, Kr[8] * p2));
            const float zc  = fmaxf(ph2, 0.1f);
            const float gz  = (ph2 > 0.1f) ? 1.f : ((ph2 == 0.1f) ? 0.5f : 0.f);
            const float invz = 1.0f / zc;
            const float u = ph0 * invz;
            const float v = ph1 * invz;
            const float wu = sWU[i], wv = sWV[i];
            const float ru = (u - sU[i]) * wu;
            const float rv = (v - sV[i]) * wv;
            const float d0y = fmaf(Kr[0], av, Kr[2] * bv);
            const float d1y = fmaf(Kr[3], av, Kr[5] * bv);
            const float d2y = fmaf(Kr[6], av, Kr[8] * bv);
            const float su_ = wu * invz;
            const float sv_ = wv * invz;
            const float ug = u * gz;
            const float vg = v * gz;
            const float Ju0 = fmaf(-ug, Kr[6], Kr[0]) * su_;
            const float Ju1 = fmaf(-ug, Kr[7], Kr[1]) * su_;
            const float Ju2 = fmaf(-ug, Kr[8], Kr[2]) * su_;
            const float Ju3 = fmaf(-ug, d2y,  d0y ) * su_;
            const float Jv0 = fmaf(-vg, Kr[6], Kr[3]) * sv_;
            const float Jv1 = fmaf(-vg, Kr[7], Kr[4]) * sv_;
            const float Jv2 = fmaf(-vg, Kr[8], Kr[5]) * sv_;
            const float Jv3 = fmaf(-vg, d2y,  d1y ) * sv_;
            acc[0] = fmaf(Ju0, Ju0, fmaf(Jv0, Jv0, acc[0]));
            acc[1] = fmaf(Ju0, Ju1, fmaf(Jv0, Jv1, acc[1]));
            acc[2] = fmaf(Ju0, Ju2, fmaf(Jv0, Jv2, acc[2]));
            acc[3] = fmaf(Ju0, Ju3, fmaf(Jv0, Jv3, acc[3]));
            acc[4] = fmaf(Ju1, Ju1, fmaf(Jv1, Jv1, acc[4]));
            acc[5] = fmaf(Ju1, Ju2, fmaf(Jv1, Jv2, acc[5]));
            acc[6] = fmaf(Ju1, Ju3, fmaf(Jv1, Jv3, acc[6]));
            acc[7] = fmaf(Ju2, Ju2, fmaf(Jv2, Jv2, acc[7]));
            acc[8] = fmaf(Ju2, Ju3, fmaf(Jv2, Jv3, acc[8]));
            acc[9] = fmaf(Ju3, Ju3, fmaf(Jv3, Jv3, acc[9]));
            acc[10] = fmaf(Ju0, ru, fmaf(Jv0, rv, acc[10]));
            acc[11] = fmaf(Ju1, ru, fmaf(Jv1, rv, acc[11]));
            acc[12] = fmaf(Ju2, ru, fmaf(Jv2, rv, acc[12]));
            acc[13] = fmaf(Ju3, ru, fmaf(Jv3, rv, acc[13]));
            acc[14] = fmaf(ru, ru, fmaf(rv, rv, acc[14]));
        }
        // warp butterfly reduce
#pragma unroll
        for (int o = 16; o > 0; o >>= 1) {
#pragma unroll
            for (int k = 0; k < 15; k++)
                acc[k] += __shfl_xor_sync(0xffffffffu, acc[k], o);
        }
        if (lane == 0) {
#pragma unroll
            for (int k = 0; k < 15; k++) red[buf][wid][k] = acc[k];
        }
        __syncthreads();
        // every thread gathers block total (reuse acc storage)
#pragma unroll
        for (int k = 0; k < 15; k++)
            acc[k] = red[buf][0][k] + red[buf][1][k];
        buf ^= 1;   // next pass writes the other buffer (WAR-safe)
    };

    // ---- initial pass at pose_init ----
    do_pass();
#pragma unroll
    for (int k = 0; k < 10; k++) jt[k] = acc[k];
#pragma unroll
    for (int k = 0; k < 4; k++) gr[k] = acc[10 + k];
    cst = 0.5f * acc[14];

    float stepv[4], pn[4];

    // ---- LM iterations ----
    for (int it = 0; it < NUM_ITER; it++) {
        // jtj_lm = jtj + clip(diag)/radius on diagonal; fp32 solve (every thread)
        {
            float A[4][4], bvec[4], xx[4];
            A[0][0] = jt[0]; A[0][1] = jt[1]; A[0][2] = jt[2]; A[0][3] = jt[3];
            A[1][0] = jt[1]; A[1][1] = jt[4]; A[1][2] = jt[5]; A[1][3] = jt[6];
            A[2][0] = jt[2]; A[2][1] = jt[5]; A[2][2] = jt[7]; A[2][3] = jt[8];
            A[3][0] = jt[3]; A[3][1] = jt[6]; A[3][2] = jt[8]; A[3][3] = jt[9];
            const float dg[4] = {jt[0], jt[4], jt[7], jt[9]};
#pragma unroll
            for (int i = 0; i < 4; i++) {
                const float d = fminf(fmaxf(dg[i], 1e-6f), 1e32f);
                A[i][i] += d / radius;
                bvec[i] = gr[i];
            }
            solve4f(A, bvec, xx);
#pragma unroll
            for (int i = 0; i < 4; i++) {
                stepv[i] = -xx[i];
                pn[i] = pose[i] + stepv[i];
            }
        }
        sincosf(pn[3], &sy, &cy);
        tx = pn[0]; ty = pn[1]; tz = pn[2];

        do_pass();

        const float cn = 0.5f * acc[14];
        // model_cost_change = -step . (grad + 0.5*jtj*step)
        const float Hs0 = jt[0]*stepv[0] + jt[1]*stepv[1] + jt[2]*stepv[2] + jt[3]*stepv[3];
        const float Hs1 = jt[1]*stepv[0] + jt[4]*stepv[1] + jt[5]*stepv[2] + jt[6]*stepv[3];
        const float Hs2 = jt[2]*stepv[0] + jt[5]*stepv[1] + jt[7]*stepv[2] + jt[8]*stepv[3];
        const float Hs3 = jt[3]*stepv[0] + jt[6]*stepv[1] + jt[8]*stepv[2] + jt[9]*stepv[3];
        const float mcc = -(stepv[0] * (gr[0] + 0.5f * Hs0) +
                            stepv[1] * (gr[1] + 0.5f * Hs1) +
                            stepv[2] * (gr[2] + 0.5f * Hs2) +
                            stepv[3] * (gr[3] + 0.5f * Hs3));
        const float rel = (cst - cn) / mcc;
        const bool succ = (rel >= 1e-3f) && (mcc > 0.0f);
        if (succ) {
            const float tmp = 2.f * rel - 1.f;
            const float den = fmaxf(1.f - tmp * tmp * tmp, 1.f / 3.f);
            radius = fminf(radius / den, 1e16f);
            dec = 2.f;
#pragma unroll
            for (int k = 0; k < 10; k++) jt[k] = acc[k];
#pragma unroll
            for (int k = 0; k < 4; k++) gr[k] = acc[10 + k];
            cst = cn;
#pragma unroll
            for (int k = 0; k < 4; k++) pose[k] = pn[k];
        } else {
            radius = radius / dec;
            dec *= 2.f;
        }
        // If the step was rejected the NEXT pass must run at the accepted
        // pose again; restore broadcast trig/translation for the solve+pass.
        if (!succ || it == NUM_ITER - 1) {
            sincosf(pose[3], &sy, &cy);
            tx = pose[0]; ty = pose[1]; tz = pose[2];
        }
    }

    // ---- outputs + GN step (reuses carried jtj/grad: identical to
    //      recomputing J,r at the accepted pose) ----
    if (tid == 0) {
        float* __restrict__ out_pose = out + (size_t)b * 4;
        float* __restrict__ out_cost = out + (size_t)4 * B + b;
        float* __restrict__ out_plus = out + (size_t)5 * B + (size_t)b * 4;
#pragma unroll
        for (int k = 0; k < 4; k++) out_pose[k] = pose[k];
        *out_cost = cst;

        float A[4][4], bvec[4], xx[4];
        A[0][0] = jt[0]; A[0][1] = jt[1]; A[0][2] = jt[2]; A[0][3] = jt[3];
        A[1][0] = jt[1]; A[1][1] = jt[4]; A[1][2] = jt[5]; A[1][3] = jt[6];
        A[2][0] = jt[2]; A[2][1] = jt[5]; A[2][2] = jt[7]; A[2][3] = jt[8];
        A[3][0] = jt[3]; A[3][1] = jt[6]; A[3][2] = jt[8]; A[3][3] = jt[9];
#pragma unroll
        for (int i = 0; i < 4; i++) {
            A[i][i] += 1e-5f;          // EPS * eye
            bvec[i] = gr[i];
        }
        solve4f(A, bvec, xx);
#pragma unroll
        for (int k = 0; k < 4; k++)
            out_plus[k] = pose[k] - xx[k];
    }
}

extern "C" void kernel_launch(void* const* d_in, const int* in_sizes, int n_in,
                              void* d_out, int out_size) {
    const float* x3d       = (const float*)d_in[0];
    const float* x2d       = (const float*)d_in[1];
    const float* w2d       = (const float*)d_in[2];
    const float* pose_init = (const float*)d_in[3];
    const float* cam_mats  = (const float*)d_in[4];
    const int B = in_sizes[3] / 4;
    float* out = (float*)d_out;
    lm_kernel<<<B, THREADS>>>(x3d, x2d, w2d, pose_init, cam_mats, out, B);
}

// round 8
// speedup vs baseline: 6.2946x; 1.5466x over previous
#include <cuda_runtime.h>

// LM pose solver: B=4096 batches, N=512 points, DOF=4 (tx,ty,tz,yaw).
// One 32-thread CTA (single warp) per batch, 16 points/thread processed as
// 8 packed f32x2 point-pairs. Pinhole-K specialized fast path (exact zeros
// make it bit-identical to the general formula); runtime fallback otherwise.
// 11 fused residual+jacobian reduction passes; warp-synchronous (no
// __syncthreads in the hot loop). All scalar LM bookkeeping done redundantly
// by every lane. GN step reuses the carried jtj/grad.

#define NPTS     512
#define THREADS  32
#define NPAIRS   (NPTS / 2 / THREADS)   // 8
#define NPT      (NPTS / THREADS)       // 16 (fallback path)
#define NUM_ITER 10

typedef unsigned long long u64;

__device__ __forceinline__ u64 pk2(float lo, float hi) {
    u64 r; asm("mov.b64 %0,{%1,%2};" : "=l"(r) : "f"(lo), "f"(hi)); return r;
}
__device__ __forceinline__ u64 pkb(float s) { return pk2(s, s); }
__device__ __forceinline__ void unpk2(u64 a, float& lo, float& hi) {
    asm("mov.b64 {%0,%1},%2;" : "=f"(lo), "=f"(hi) : "l"(a));
}
__device__ __forceinline__ u64 f2fma(u64 a, u64 b, u64 c) {
    u64 d; asm("fma.rn.f32x2 %0,%1,%2,%3;" : "=l"(d) : "l"(a), "l"(b), "l"(c)); return d;
}
__device__ __forceinline__ u64 f2mul(u64 a, u64 b) {
    u64 d; asm("mul.rn.f32x2 %0,%1,%2;" : "=l"(d) : "l"(a), "l"(b)); return d;
}
__device__ __forceinline__ u64 f2add(u64 a, u64 b) {
    u64 d; asm("add.rn.f32x2 %0,%1,%2;" : "=l"(d) : "l"(a), "l"(b)); return d;
}
__device__ __forceinline__ u64 ld2(const float* s, int j) {
    const float2 v = reinterpret_cast<const float2*>(s)[j];
    return pk2(v.x, v.y);
}

// fp32 Gaussian elimination, no pivoting (A is SPD + LM damping).
__device__ __forceinline__ void solve4f(float A[4][4], float bv[4], float x[4]) {
#pragma unroll
    for (int k = 0; k < 4; k++) {
        const float inv = 1.0f / A[k][k];
#pragma unroll
        for (int i = 0; i < 4; i++) {
            if (i > k) {
                const float f = A[i][k] * inv;
#pragma unroll
                for (int j = 0; j < 4; j++)
                    if (j >= k) A[i][j] = fmaf(-f, A[k][j], A[i][j]);
                bv[i] = fmaf(-f, bv[k], bv[i]);
            }
        }
    }
#pragma unroll
    for (int k = 3; k >= 0; k--) {
        float s = bv[k];
#pragma unroll
        for (int j = 0; j < 4; j++)
            if (j > k) s = fmaf(-A[k][j], x[j], s);
        x[k] = s / A[k][k];
    }
}

__global__ void __launch_bounds__(THREADS, 15) lm_kernel(
    const float* __restrict__ x3d,
    const float* __restrict__ x2d,
    const float* __restrict__ w2d,
    const float* __restrict__ pose_init,
    const float* __restrict__ cam,
    float* __restrict__ out,   // [4B pose | B cost | 4B pose_plus]
    int B)
{
    __shared__ float sX[NPTS], sY[NPTS], sZ[NPTS];
    __shared__ float sWU[NPTS], sWV[NPTS], sNUW[NPTS], sNVW[NPTS];

    const int b   = blockIdx.x;
    const int tid = threadIdx.x;

    // ---- stage point data into smem (SoA), one-time cost ----
    const float*  __restrict__ xb = x3d + (size_t)b * NPTS * 3;
    const float2* __restrict__ ub = (const float2*)(x2d + (size_t)b * NPTS * 2);
    const float2* __restrict__ wb = (const float2*)(w2d + (size_t)b * NPTS * 2);
    for (int i = tid; i < NPTS; i += THREADS) {
        sX[i] = xb[3 * i + 0];
        sY[i] = xb[3 * i + 1];
        sZ[i] = xb[3 * i + 2];
        const float2 u2 = ub[i];
        const float2 w2 = wb[i];
        sWU[i]  = w2.x;            sWV[i]  = w2.y;
        sNUW[i] = -(u2.x * w2.x);  sNVW[i] = -(u2.y * w2.y);
    }

    float Kr[9];
#pragma unroll
    for (int k = 0; k < 9; k++) Kr[k] = cam[(size_t)b * 9 + k];
    // Pinhole structure check: with exact zeros the specialized math is
    // BIT-IDENTICAL to the general formula (fmaf(x,0,y)==y exactly).
    const bool pin = (Kr[1] == 0.f) && (Kr[3] == 0.f) && (Kr[6] == 0.f) &&
                     (Kr[7] == 0.f) && (Kr[8] == 1.f);

    float pose[4];
#pragma unroll
    for (int k = 0; k < 4; k++) pose[k] = pose_init[b * 4 + k];
    float jt[10], gr[4];
    float cst = 0.f, radius = 30.0f, dec = 2.0f;

    float cy, sy;
    sincosf(pose[3], &sy, &cy);
    float tx = pose[0], ty = pose[1], tz = pose[2];

    __syncwarp();   // staging visible warp-wide

    float t[15];

    // One fused residual+jacobian reduction pass at (tx,ty,tz,cy,sy).
    // On exit every lane holds the batch-wide sums in t[0..14].
    auto do_pass = [&]() {
        if (pin) {
            const float fx = Kr[0], cx = Kr[2], fy = Kr[4], cyk = Kr[5];
            u64 A0 = 0, A2 = 0, A3 = 0, A4 = 0, A5 = 0, A6 = 0, A7 = 0,
                A8 = 0, A9 = 0, A10 = 0, A11 = 0, A12 = 0, A13 = 0, A14 = 0;
            const u64 TX = pkb(tx), TY = pkb(ty), TZ = pkb(tz), nTZ = pkb(-tz);
            const u64 CYr = pkb(cy), SYr = pkb(sy), nSY = pkb(-sy);
            const u64 FX = pkb(fx), CX = pkb(cx), FY = pkb(fy), CYK = pkb(cyk);
            const u64 M1 = pkb(-1.0f);
#pragma unroll 4
            for (int p = 0; p < NPAIRS; p++) {
                const int j = tid + p * THREADS;        // float2 index: points (2j, 2j+1)
                const u64 Px = ld2(sX, j), Py = ld2(sY, j), Pz = ld2(sZ, j);
                const u64 p0 = f2fma(CYr, Px, f2fma(SYr, Pz, TX));
                const u64 p1 = f2add(Py, TY);
                const u64 p2 = f2fma(nSY, Px, f2fma(CYr, Pz, TZ));
                const u64 av = f2add(p2, nTZ);          //  -s*X + c*Z
                const u64 bv = f2fma(p0, M1, TX);       // -(c*X + s*Z)
                const u64 ph0 = f2fma(FX, p0, f2mul(CX, p2));
                const u64 ph1 = f2fma(FY, p1, f2mul(CYK, p2));
                float z0, z1; unpk2(p2, z0, z1);        // ph2 == p2 (K8==1)
                const float i0 = 1.0f / fmaxf(z0, 0.1f);
                const float i1 = 1.0f / fmaxf(z1, 0.1f);
                const float g0 = (z0 > 0.1f) ? 1.f : ((z0 == 0.1f) ? 0.5f : 0.f);
                const float g1 = (z1 > 0.1f) ? 1.f : ((z1 == 0.1f) ? 0.5f : 0.f);
                const u64 invz = pk2(i0, i1);
                const u64 gz   = pk2(g0, g1);
                const u64 WU = ld2(sWU, j), WV = ld2(sWV, j);
                const u64 u  = f2mul(ph0, invz);
                const u64 v  = f2mul(ph1, invz);
                const u64 ru = f2fma(u, WU, ld2(sNUW, j));   // u*wu - x2d_u*wu
                const u64 rv = f2fma(v, WV, ld2(sNVW, j));
                const u64 su = f2mul(WU, invz);
                const u64 sv = f2mul(WV, invz);
                const u64 ug = f2mul(u, gz);
                const u64 vg = f2mul(v, gz);
                const u64 Ju0 = f2mul(FX, su);
                const u64 Jv1 = f2mul(FY, sv);
                const u64 Ju2 = f2mul(f2fma(ug, M1, CX), su);
                const u64 Jv2 = f2mul(f2fma(vg, M1, CYK), sv);
                const u64 Ju3 = f2fma(Ju0, av, f2mul(Ju2, bv));
                const u64 Jv3 = f2mul(Jv2, bv);
                A0  = f2fma(Ju0, Ju0, A0);
                A2  = f2fma(Ju0, Ju2, A2);
                A3  = f2fma(Ju0, Ju3, A3);
                A4  = f2fma(Jv1, Jv1, A4);
                A5  = f2fma(Jv1, Jv2, A5);
                A6  = f2fma(Jv1, Jv3, A6);
                A7  = f2fma(Ju2, Ju2, f2fma(Jv2, Jv2, A7));
                A8  = f2fma(Ju2, Ju3, f2fma(Jv2, Jv3, A8));
                A9  = f2fma(Ju3, Ju3, f2fma(Jv3, Jv3, A9));
                A10 = f2fma(Ju0, ru, A10);
                A11 = f2fma(Jv1, rv, A11);
                A12 = f2fma(Ju2, ru, f2fma(Jv2, rv, A12));
                A13 = f2fma(Ju3, ru, f2fma(Jv3, rv, A13));
                A14 = f2fma(ru, ru, f2fma(rv, rv, A14));
            }
            float l, h;
            unpk2(A0, l, h);  t[0]  = l + h;  t[1] = 0.f;  // Ju1==Jv0==0 exactly
            unpk2(A2, l, h);  t[2]  = l + h;
            unpk2(A3, l, h);  t[3]  = l + h;
            unpk2(A4, l, h);  t[4]  = l + h;
            unpk2(A5, l, h);  t[5]  = l + h;
            unpk2(A6, l, h);  t[6]  = l + h;
            unpk2(A7, l, h);  t[7]  = l + h;
            unpk2(A8, l, h);  t[8]  = l + h;
            unpk2(A9, l, h);  t[9]  = l + h;
            unpk2(A10, l, h); t[10] = l + h;
            unpk2(A11, l, h); t[11] = l + h;
            unpk2(A12, l, h); t[12] = l + h;
            unpk2(A13, l, h); t[13] = l + h;
            unpk2(A14, l, h); t[14] = l + h;
        } else {
            // general-K scalar fallback (not taken for this dataset)
            float a[15];
#pragma unroll
            for (int k = 0; k < 15; k++) a[k] = 0.f;
#pragma unroll 1
            for (int p = 0; p < NPT; p++) {
                const int i = tid + p * THREADS;
                const float X = sX[i], Y = sY[i], Z = sZ[i];
                const float p0 = fmaf(cy, X, fmaf(sy, Z, tx));
                const float p1 = Y + ty;
                const float p2 = fmaf(-sy, X, fmaf(cy, Z, tz));
                const float av = p2 - tz;
                const float bvv = tx - p0;
                const float ph0 = fmaf(Kr[0], p0, fmaf(Kr[1], p1, Kr[2] * p2));
                const float ph1 = fmaf(Kr[3], p0, fmaf(Kr[4], p1, Kr[5] * p2));
                const float ph2 = fmaf(Kr[6], p0, fmaf(Kr[7], p1, Kr[8] * p2));
                const float zc  = fmaxf(ph2, 0.1f);
                const float gz  = (ph2 > 0.1f) ? 1.f : ((ph2 == 0.1f) ? 0.5f : 0.f);
                const float invz = 1.0f / zc;
                const float u = ph0 * invz;
                const float v = ph1 * invz;
                const float wu = sWU[i], wv = sWV[i];
                const float ru = fmaf(u, wu, sNUW[i]);
                const float rv = fmaf(v, wv, sNVW[i]);
                const float d0y = fmaf(Kr[0], av, Kr[2] * bvv);
                const float d1y = fmaf(Kr[3], av, Kr[5] * bvv);
                const float d2y = fmaf(Kr[6], av, Kr[8] * bvv);
                const float su_ = wu * invz;
                const float sv_ = wv * invz;
                const float ug = u * gz;
                const float vg = v * gz;
                const float Ju0 = fmaf(-ug, Kr[6], Kr[0]) * su_;
                const float Ju1 = fmaf(-ug, Kr[7], Kr[1]) * su_;
                const float Ju2 = fmaf(-ug, Kr[8], Kr[2]) * su_;
                const float Ju3 = fmaf(-ug, d2y,  d0y ) * su_;
                const float Jv0 = fmaf(-vg, Kr[6], Kr[3]) * sv_;
                const float Jv1 = fmaf(-vg, Kr[7], Kr[4]) * sv_;
                const float Jv2 = fmaf(-vg, Kr[8], Kr[5]) * sv_;
                const float Jv3 = fmaf(-vg, d2y,  d1y ) * sv_;
                a[0] = fmaf(Ju0, Ju0, fmaf(Jv0, Jv0, a[0]));
                a[1] = fmaf(Ju0, Ju1, fmaf(Jv0, Jv1, a[1]));
                a[2] = fmaf(Ju0, Ju2, fmaf(Jv0, Jv2, a[2]));
                a[3] = fmaf(Ju0, Ju3, fmaf(Jv0, Jv3, a[3]));
                a[4] = fmaf(Ju1, Ju1, fmaf(Jv1, Jv1, a[4]));
                a[5] = fmaf(Ju1, Ju2, fmaf(Jv1, Jv2, a[5]));
                a[6] = fmaf(Ju1, Ju3, fmaf(Jv1, Jv3, a[6]));
                a[7] = fmaf(Ju2, Ju2, fmaf(Jv2, Jv2, a[7]));
                a[8] = fmaf(Ju2, Ju3, fmaf(Jv2, Jv3, a[8]));
                a[9] = fmaf(Ju3, Ju3, fmaf(Jv3, Jv3, a[9]));
                a[10] = fmaf(Ju0, ru, fmaf(Jv0, rv, a[10]));
                a[11] = fmaf(Ju1, ru, fmaf(Jv1, rv, a[11]));
                a[12] = fmaf(Ju2, ru, fmaf(Jv2, rv, a[12]));
                a[13] = fmaf(Ju3, ru, fmaf(Jv3, rv, a[13]));
                a[14] = fmaf(ru, ru, fmaf(rv, rv, a[14]));
            }
#pragma unroll
            for (int k = 0; k < 15; k++) t[k] = a[k];
        }
        // single-warp butterfly reduce; every lane ends with the full sums
#pragma unroll
        for (int o = 16; o > 0; o >>= 1) {
#pragma unroll
            for (int k = 0; k < 15; k++)
                t[k] += __shfl_xor_sync(0xffffffffu, t[k], o);
        }
    };

    // ---- initial pass at pose_init ----
    do_pass();
#pragma unroll
    for (int k = 0; k < 10; k++) jt[k] = t[k];
#pragma unroll
    for (int k = 0; k < 4; k++) gr[k] = t[10 + k];
    cst = 0.5f * t[14];

    float stepv[4], pn[4];

    // ---- LM iterations ----
    for (int it = 0; it < NUM_ITER; it++) {
        {
            float A[4][4], bvec[4], xx[4];
            A[0][0] = jt[0]; A[0][1] = jt[1]; A[0][2] = jt[2]; A[0][3] = jt[3];
            A[1][0] = jt[1]; A[1][1] = jt[4]; A[1][2] = jt[5]; A[1][3] = jt[6];
            A[2][0] = jt[2]; A[2][1] = jt[5]; A[2][2] = jt[7]; A[2][3] = jt[8];
            A[3][0] = jt[3]; A[3][1] = jt[6]; A[3][2] = jt[8]; A[3][3] = jt[9];
            const float dg[4] = {jt[0], jt[4], jt[7], jt[9]};
#pragma unroll
            for (int i = 0; i < 4; i++) {
                const float d = fminf(fmaxf(dg[i], 1e-6f), 1e32f);
                A[i][i] += d / radius;
                bvec[i] = gr[i];
            }
            solve4f(A, bvec, xx);
#pragma unroll
            for (int i = 0; i < 4; i++) {
                stepv[i] = -xx[i];
                pn[i] = pose[i] + stepv[i];
            }
        }
        sincosf(pn[3], &sy, &cy);
        tx = pn[0]; ty = pn[1]; tz = pn[2];

        do_pass();

        const float cn = 0.5f * t[14];
        const float Hs0 = jt[0]*stepv[0] + jt[1]*stepv[1] + jt[2]*stepv[2] + jt[3]*stepv[3];
        const float Hs1 = jt[1]*stepv[0] + jt[4]*stepv[1] + jt[5]*stepv[2] + jt[6]*stepv[3];
        const float Hs2 = jt[2]*stepv[0] + jt[5]*stepv[1] + jt[7]*stepv[2] + jt[8]*stepv[3];
        const float Hs3 = jt[3]*stepv[0] + jt[6]*stepv[1] + jt[8]*stepv[2] + jt[9]*stepv[3];
        const float mcc = -(stepv[0] * (gr[0] + 0.5f * Hs0) +
                            stepv[1] * (gr[1] + 0.5f * Hs1) +
                            stepv[2] * (gr[2] + 0.5f * Hs2) +
                            stepv[3] * (gr[3] + 0.5f * Hs3));
        const float rel = (cst - cn) / mcc;
        const bool succ = (rel >= 1e-3f) && (mcc > 0.0f);
        if (succ) {
            const float tmp = 2.f * rel - 1.f;
            const float den = fmaxf(1.f - tmp * tmp * tmp, 1.f / 3.f);
            radius = fminf(radius / den, 1e16f);
            dec = 2.f;
#pragma unroll
            for (int k = 0; k < 10; k++) jt[k] = t[k];
#pragma unroll
            for (int k = 0; k < 4; k++) gr[k] = t[10 + k];
            cst = cn;
#pragma unroll
            for (int k = 0; k < 4; k++) pose[k] = pn[k];
        } else {
            radius = radius / dec;
            dec *= 2.f;
            // next pass must run at the accepted pose again
            sincosf(pose[3], &sy, &cy);
            tx = pose[0]; ty = pose[1]; tz = pose[2];
        }
    }

    // ---- outputs + GN step (reuses carried jtj/grad) ----
    if (tid == 0) {
        float* __restrict__ out_pose = out + (size_t)b * 4;
        float* __restrict__ out_cost = out + (size_t)4 * B + b;
        float* __restrict__ out_plus = out + (size_t)5 * B + (size_t)b * 4;
#pragma unroll
        for (int k = 0; k < 4; k++) out_pose[k] = pose[k];
        *out_cost = cst;

        float A[4][4], bvec[4], xx[4];
        A[0][0] = jt[0]; A[0][1] = jt[1]; A[0][2] = jt[2]; A[0][3] = jt[3];
        A[1][0] = jt[1]; A[1][1] = jt[4]; A[1][2] = jt[5]; A[1][3] = jt[6];
        A[2][0] = jt[2]; A[2][1] = jt[5]; A[2][2] = jt[7]; A[2][3] = jt[8];
        A[3][0] = jt[3]; A[3][1] = jt[6]; A[3][2] = jt[8]; A[3][3] = jt[9];
#pragma unroll
        for (int i = 0; i < 4; i++) {
            A[i][i] += 1e-5f;          // EPS * eye
            bvec[i] = gr[i];
        }
        solve4f(A, bvec, xx);
#pragma unroll
        for (int k = 0; k < 4; k++)
            out_plus[k] = pose[k] - xx[k];
    }
}

extern "C" void kernel_launch(void* const* d_in, const int* in_sizes, int n_in,
                              void* d_out, int out_size) {
    const float* x3d       = (const float*)d_in[0];
    const float* x2d       = (const float*)d_in[1];
    const float* w2d       = (const float*)d_in[2];
    const float* pose_init = (const float*)d_in[3];
    const float* cam_mats  = (const float*)d_in[4];
    const int B = in_sizes[3] / 4;
    float* out = (float*)d_out;
    lm_kernel<<<B, THREADS>>>(x3d, x2d, w2d, pose_init, cam_mats, out, B);
}

// round 11
// speedup vs baseline: 7.4007x; 1.1757x over previous
#include <cuda_runtime.h>

// LM pose solver: B=4096 batches, N=512 points, DOF=4 (tx,ty,tz,yaw).
// One 32-thread CTA (single warp) per batch; 8 packed f32x2 point-pairs per
// lane. Pinhole-K fast path (exact zeros -> bit-identical to general form).
// This round: rcp.approx for 1/z, LDS.128 pair-packed smem, fully-unrolled
// pair loop, butterfly reduce trimmed to 14 values (redux.f32 doesn't exist
// on sm_103 -- ptxas-verified).

#define NPTS     512
#define NPAIRS_T 256                     // total float2 pairs
#define THREADS  32
#define NPAIRS   (NPAIRS_T / THREADS)    // 8 pairs per lane
#define NUM_ITER 10

typedef unsigned long long u64;

__device__ __forceinline__ u64 pk2(float lo, float hi) {
    u64 r; asm("mov.b64 %0,{%1,%2};" : "=l"(r) : "f"(lo), "f"(hi)); return r;
}
__device__ __forceinline__ u64 pkb(float s) { return pk2(s, s); }
__device__ __forceinline__ void unpk2(u64 a, float& lo, float& hi) {
    asm("mov.b64 {%0,%1},%2;" : "=f"(lo), "=f"(hi) : "l"(a));
}
__device__ __forceinline__ u64 f2fma(u64 a, u64 b, u64 c) {
    u64 d; asm("fma.rn.f32x2 %0,%1,%2,%3;" : "=l"(d) : "l"(a), "l"(b), "l"(c)); return d;
}
__device__ __forceinline__ u64 f2mul(u64 a, u64 b) {
    u64 d; asm("mul.rn.f32x2 %0,%1,%2;" : "=l"(d) : "l"(a), "l"(b)); return d;
}
__device__ __forceinline__ u64 f2add(u64 a, u64 b) {
    u64 d; asm("add.rn.f32x2 %0,%1,%2;" : "=l"(d) : "l"(a), "l"(b)); return d;
}
__device__ __forceinline__ float frcp(float x) {
    float r; asm("rcp.approx.f32 %0, %1;" : "=f"(r) : "f"(x)); return r;
}
// warp butterfly sum (all lanes get total)
__device__ __forceinline__ float wsum(float x) {
#pragma unroll
    for (int o = 16; o > 0; o >>= 1)
        x += __shfl_xor_sync(0xffffffffu, x, o);
    return x;
}

// fp32 Gaussian elimination, no pivoting (A is SPD + LM damping).
__device__ __forceinline__ void solve4f(float A[4][4], float bv[4], float x[4]) {
#pragma unroll
    for (int k = 0; k < 4; k++) {
        const float inv = 1.0f / A[k][k];
#pragma unroll
        for (int i = 0; i < 4; i++) {
            if (i > k) {
                const float f = A[i][k] * inv;
#pragma unroll
                for (int j = 0; j < 4; j++)
                    if (j >= k) A[i][j] = fmaf(-f, A[k][j], A[i][j]);
                bv[i] = fmaf(-f, bv[k], bv[i]);
            }
        }
    }
#pragma unroll
    for (int k = 3; k >= 0; k--) {
        float s = bv[k];
#pragma unroll
        for (int j = 0; j < 4; j++)
            if (j > k) s = fmaf(-A[k][j], x[j], s);
        x[k] = s / A[k][k];
    }
}

__global__ void __launch_bounds__(THREADS, 15) lm_kernel(
    const float* __restrict__ x3d,
    const float* __restrict__ x2d,
    const float* __restrict__ w2d,
    const float* __restrict__ pose_init,
    const float* __restrict__ cam,
    float* __restrict__ out,   // [4B pose | B cost | 4B pose_plus]
    int B)
{
    // pair-packed layout: one pair (2 points) = sA.xyzw=(X0,X1,Y0,Y1),
    // sB=(Z0,Z1,WU0,WU1), sC=(WV0,WV1,NUW0,NUW1), sD=(NVW0,NVW1)
    __shared__ float4 sA[NPAIRS_T], sB[NPAIRS_T], sC[NPAIRS_T];
    __shared__ float2 sD[NPAIRS_T];

    const int b   = blockIdx.x;
    const int tid = threadIdx.x;

    // ---- stage point data (one-time) ----
    const float*  __restrict__ xb = x3d + (size_t)b * NPTS * 3;
    const float2* __restrict__ ub = (const float2*)(x2d + (size_t)b * NPTS * 2);
    const float2* __restrict__ wb = (const float2*)(w2d + (size_t)b * NPTS * 2);
    for (int j = tid; j < NPAIRS_T; j += THREADS) {
        const float X0 = xb[6*j+0], Y0 = xb[6*j+1], Z0 = xb[6*j+2];
        const float X1 = xb[6*j+3], Y1 = xb[6*j+4], Z1 = xb[6*j+5];
        const float2 u0 = ub[2*j], u1 = ub[2*j+1];
        const float2 w0 = wb[2*j], w1 = wb[2*j+1];
        sA[j] = make_float4(X0, X1, Y0, Y1);
        sB[j] = make_float4(Z0, Z1, w0.x, w1.x);
        sC[j] = make_float4(w0.y, w1.y, -(u0.x*w0.x), -(u1.x*w1.x));
        sD[j] = make_float2(-(u0.y*w0.y), -(u1.y*w1.y));
    }

    float Kr[9];
#pragma unroll
    for (int k = 0; k < 9; k++) Kr[k] = cam[(size_t)b * 9 + k];
    // Pinhole check: with exact zeros the specialized math is BIT-IDENTICAL
    // to the general formula (fmaf(x,0,y)==y exactly).
    const bool pin = (Kr[1] == 0.f) && (Kr[3] == 0.f) && (Kr[6] == 0.f) &&
                     (Kr[7] == 0.f) && (Kr[8] == 1.f);

    float pose[4];
#pragma unroll
    for (int k = 0; k < 4; k++) pose[k] = pose_init[b * 4 + k];
    float jt[10], gr[4];
    float cst = 0.f, radius = 30.0f, dec = 2.0f;

    float cy, sy;
    sincosf(pose[3], &sy, &cy);
    float tx = pose[0], ty = pose[1], tz = pose[2];

    __syncwarp();   // staging visible warp-wide

    float t[15];

    // One fused residual+jacobian reduction pass at (tx,ty,tz,cy,sy).
    // On exit every lane holds the batch-wide sums in t[0..14]
    // (t[14]=2*cost is reduced FIRST to shorten the accept-decision path).
    auto do_pass = [&]() {
        if (pin) {
            const float fx = Kr[0], cx = Kr[2], fy = Kr[4], cyk = Kr[5];
            u64 A0 = 0, A2 = 0, A3 = 0, A4 = 0, A5 = 0, A6 = 0, A7 = 0,
                A8 = 0, A9 = 0, A10 = 0, A11 = 0, A12 = 0, A13 = 0, A14 = 0;
            const u64 TX = pkb(tx), TY = pkb(ty), TZ = pkb(tz), nTZ = pkb(-tz);
            const u64 CYr = pkb(cy), SYr = pkb(sy), nSY = pkb(-sy);
            const u64 FX = pkb(fx), CX = pkb(cx), FY = pkb(fy), CYK = pkb(cyk);
            const u64 M1 = pkb(-1.0f);
#pragma unroll
            for (int p = 0; p < NPAIRS; p++) {
                const int j = tid + p * THREADS;
                const float4 a4 = sA[j];
                const float4 b4 = sB[j];
                const float4 c4 = sC[j];
                const float2 d2 = sD[j];
                const u64 Px = pk2(a4.x, a4.y), Py = pk2(a4.z, a4.w);
                const u64 Pz = pk2(b4.x, b4.y), WU = pk2(b4.z, b4.w);
                const u64 WV = pk2(c4.x, c4.y), NUW = pk2(c4.z, c4.w);
                const u64 NVW = pk2(d2.x, d2.y);
                const u64 p0 = f2fma(CYr, Px, f2fma(SYr, Pz, TX));
                const u64 p1 = f2add(Py, TY);
                const u64 p2 = f2fma(nSY, Px, f2fma(CYr, Pz, TZ));
                const u64 av = f2add(p2, nTZ);          //  -s*X + c*Z
                const u64 bv = f2fma(p0, M1, TX);       // -(c*X + s*Z)
                const u64 ph0 = f2fma(FX, p0, f2mul(CX, p2));
                const u64 ph1 = f2fma(FY, p1, f2mul(CYK, p2));
                float z0, z1; unpk2(p2, z0, z1);        // ph2 == p2 (K8==1)
                const float i0 = frcp(fmaxf(z0, 0.1f));
                const float i1 = frcp(fmaxf(z1, 0.1f));
                const float g0 = (z0 > 0.1f) ? 1.f : ((z0 == 0.1f) ? 0.5f : 0.f);
                const float g1 = (z1 > 0.1f) ? 1.f : ((z1 == 0.1f) ? 0.5f : 0.f);
                const u64 invz = pk2(i0, i1);
                const u64 gz   = pk2(g0, g1);
                const u64 u  = f2mul(ph0, invz);
                const u64 v  = f2mul(ph1, invz);
                const u64 ru = f2fma(u, WU, NUW);       // u*wu - x2d_u*wu
                const u64 rv = f2fma(v, WV, NVW);
                const u64 su = f2mul(WU, invz);
                const u64 sv = f2mul(WV, invz);
                const u64 ug = f2mul(u, gz);
                const u64 vg = f2mul(v, gz);
                const u64 Ju0 = f2mul(FX, su);
                const u64 Jv1 = f2mul(FY, sv);
                const u64 Ju2 = f2mul(f2fma(ug, M1, CX), su);
                const u64 Jv2 = f2mul(f2fma(vg, M1, CYK), sv);
                const u64 Ju3 = f2fma(Ju0, av, f2mul(Ju2, bv));
                const u64 Jv3 = f2mul(Jv2, bv);
                A0  = f2fma(Ju0, Ju0, A0);
                A2  = f2fma(Ju0, Ju2, A2);
                A3  = f2fma(Ju0, Ju3, A3);
                A4  = f2fma(Jv1, Jv1, A4);
                A5  = f2fma(Jv1, Jv2, A5);
                A6  = f2fma(Jv1, Jv3, A6);
                A7  = f2fma(Ju2, Ju2, f2fma(Jv2, Jv2, A7));
                A8  = f2fma(Ju2, Ju3, f2fma(Jv2, Jv3, A8));
                A9  = f2fma(Ju3, Ju3, f2fma(Jv3, Jv3, A9));
                A10 = f2fma(Ju0, ru, A10);
                A11 = f2fma(Jv1, rv, A11);
                A12 = f2fma(Ju2, ru, f2fma(Jv2, rv, A12));
                A13 = f2fma(Ju3, ru, f2fma(Jv3, rv, A13));
                A14 = f2fma(ru, ru, f2fma(rv, rv, A14));
            }
            float l, h;
            // cost first: shortest path to the accept decision
            unpk2(A14, l, h); t[14] = wsum(l + h);
            t[1] = 0.f;                                  // Ju1==Jv0==0 exactly
            unpk2(A0, l, h);  t[0]  = wsum(l + h);
            unpk2(A2, l, h);  t[2]  = wsum(l + h);
            unpk2(A3, l, h);  t[3]  = wsum(l + h);
            unpk2(A4, l, h);  t[4]  = wsum(l + h);
            unpk2(A5, l, h);  t[5]  = wsum(l + h);
            unpk2(A6, l, h);  t[6]  = wsum(l + h);
            unpk2(A7, l, h);  t[7]  = wsum(l + h);
            unpk2(A8, l, h);  t[8]  = wsum(l + h);
            unpk2(A9, l, h);  t[9]  = wsum(l + h);
            unpk2(A10, l, h); t[10] = wsum(l + h);
            unpk2(A11, l, h); t[11] = wsum(l + h);
            unpk2(A12, l, h); t[12] = wsum(l + h);
            unpk2(A13, l, h); t[13] = wsum(l + h);
        } else {
            // general-K fallback (not taken for this dataset)
            float a[15];
#pragma unroll
            for (int k = 0; k < 15; k++) a[k] = 0.f;
#pragma unroll 1
            for (int p = 0; p < NPAIRS; p++) {
                const int j = tid + p * THREADS;
                const float4 a4 = sA[j];
                const float4 b4 = sB[j];
                const float4 c4 = sC[j];
                const float2 d2 = sD[j];
#pragma unroll
                for (int hlf = 0; hlf < 2; hlf++) {
                    const float X = hlf ? a4.y : a4.x;
                    const float Y = hlf ? a4.w : a4.z;
                    const float Z = hlf ? b4.y : b4.x;
                    const float wu = hlf ? b4.w : b4.z;
                    const float wv = hlf ? c4.y : c4.x;
                    const float nuw = hlf ? c4.w : c4.z;
                    const float nvw = hlf ? d2.y : d2.x;
                    const float p0 = fmaf(cy, X, fmaf(sy, Z, tx));
                    const float p1 = Y + ty;
                    const float p2 = fmaf(-sy, X, fmaf(cy, Z, tz));
                    const float avv = p2 - tz;
                    const float bvv = tx - p0;
                    const float ph0 = fmaf(Kr[0], p0, fmaf(Kr[1], p1, Kr[2] * p2));
                    const float ph1 = fmaf(Kr[3], p0, fmaf(Kr[4], p1, Kr[5] * p2));
                    const float ph2 = fmaf(Kr[6], p0, fmaf(Kr[7], p1, Kr[8] * p2));
                    const float zc  = fmaxf(ph2, 0.1f);
                    const float gz  = (ph2 > 0.1f) ? 1.f : ((ph2 == 0.1f) ? 0.5f : 0.f);
                    const float invz = 1.0f / zc;
                    const float u = ph0 * invz;
                    const float v = ph1 * invz;
                    const float ru = fmaf(u, wu, nuw);
                    const float rv = fmaf(v, wv, nvw);
                    const float d0y = fmaf(Kr[0], avv, Kr[2] * bvv);
                    const float d1y = fmaf(Kr[3], avv, Kr[5] * bvv);
                    const float d2y = fmaf(Kr[6], avv, Kr[8] * bvv);
                    const float su_ = wu * invz;
                    const float sv_ = wv * invz;
                    const float ug = u * gz;
                    const float vg = v * gz;
                    const float Ju0 = fmaf(-ug, Kr[6], Kr[0]) * su_;
                    const float Ju1 = fmaf(-ug, Kr[7], Kr[1]) * su_;
                    const float Ju2 = fmaf(-ug, Kr[8], Kr[2]) * su_;
                    const float Ju3 = fmaf(-ug, d2y,  d0y ) * su_;
                    const float Jv0 = fmaf(-vg, Kr[6], Kr[3]) * sv_;
                    const float Jv1 = fmaf(-vg, Kr[7], Kr[4]) * sv_;
                    const float Jv2 = fmaf(-vg, Kr[8], Kr[5]) * sv_;
                    const float Jv3 = fmaf(-vg, d2y,  d1y ) * sv_;
                    a[0] = fmaf(Ju0, Ju0, fmaf(Jv0, Jv0, a[0]));
                    a[1] = fmaf(Ju0, Ju1, fmaf(Jv0, Jv1, a[1]));
                    a[2] = fmaf(Ju0, Ju2, fmaf(Jv0, Jv2, a[2]));
                    a[3] = fmaf(Ju0, Ju3, fmaf(Jv0, Jv3, a[3]));
                    a[4] = fmaf(Ju1, Ju1, fmaf(Jv1, Jv1, a[4]));
                    a[5] = fmaf(Ju1, Ju2, fmaf(Jv1, Jv2, a[5]));
                    a[6] = fmaf(Ju1, Ju3, fmaf(Jv1, Jv3, a[6]));
                    a[7] = fmaf(Ju2, Ju2, fmaf(Jv2, Jv2, a[7]));
                    a[8] = fmaf(Ju2, Ju3, fmaf(Jv2, Jv3, a[8]));
                    a[9] = fmaf(Ju3, Ju3, fmaf(Jv3, Jv3, a[9]));
                    a[10] = fmaf(Ju0, ru, fmaf(Jv0, rv, a[10]));
                    a[11] = fmaf(Ju1, ru, fmaf(Jv1, rv, a[11]));
                    a[12] = fmaf(Ju2, ru, fmaf(Jv2, rv, a[12]));
                    a[13] = fmaf(Ju3, ru, fmaf(Jv3, rv, a[13]));
                    a[14] = fmaf(ru, ru, fmaf(rv, rv, a[14]));
                }
            }
#pragma unroll
            for (int k = 0; k < 15; k++) t[k] = wsum(a[k]);
        }
    };

    // ---- initial pass at pose_init ----
    do_pass();
#pragma unroll
    for (int k = 0; k < 10; k++) jt[k] = t[k];
#pragma unroll
    for (int k = 0; k < 4; k++) gr[k] = t[10 + k];
    cst = 0.5f * t[14];

    float stepv[4], pn[4];

    // ---- LM iterations ----
    for (int it = 0; it < NUM_ITER; it++) {
        {
            float A[4][4], bvec[4], xx[4];
            A[0][0] = jt[0]; A[0][1] = jt[1]; A[0][2] = jt[2]; A[0][3] = jt[3];
            A[1][0] = jt[1]; A[1][1] = jt[4]; A[1][2] = jt[5]; A[1][3] = jt[6];
            A[2][0] = jt[2]; A[2][1] = jt[5]; A[2][2] = jt[7]; A[2][3] = jt[8];
            A[3][0] = jt[3]; A[3][1] = jt[6]; A[3][2] = jt[8]; A[3][3] = jt[9];
            const float dg[4] = {jt[0], jt[4], jt[7], jt[9]};
#pragma unroll
            for (int i = 0; i < 4; i++) {
                const float d = fminf(fmaxf(dg[i], 1e-6f), 1e32f);
                A[i][i] += d / radius;
                bvec[i] = gr[i];
            }
            solve4f(A, bvec, xx);
#pragma unroll
            for (int i = 0; i < 4; i++) {
                stepv[i] = -xx[i];
                pn[i] = pose[i] + stepv[i];
            }
        }
        sincosf(pn[3], &sy, &cy);
        tx = pn[0]; ty = pn[1]; tz = pn[2];

        do_pass();

        const float cn = 0.5f * t[14];
        const float Hs0 = jt[0]*stepv[0] + jt[1]*stepv[1] + jt[2]*stepv[2] + jt[3]*stepv[3];
        const float Hs1 = jt[1]*stepv[0] + jt[4]*stepv[1] + jt[5]*stepv[2] + jt[6]*stepv[3];
        const float Hs2 = jt[2]*stepv[0] + jt[5]*stepv[1] + jt[7]*stepv[2] + jt[8]*stepv[3];
        const float Hs3 = jt[3]*stepv[0] + jt[6]*stepv[1] + jt[8]*stepv[2] + jt[9]*stepv[3];
        const float mcc = -(stepv[0] * (gr[0] + 0.5f * Hs0) +
                            stepv[1] * (gr[1] + 0.5f * Hs1) +
                            stepv[2] * (gr[2] + 0.5f * Hs2) +
                            stepv[3] * (gr[3] + 0.5f * Hs3));
        const float rel = (cst - cn) / mcc;
        const bool succ = (rel >= 1e-3f) && (mcc > 0.0f);
        if (succ) {
            const float tmp = 2.f * rel - 1.f;
            const float den = fmaxf(1.f - tmp * tmp * tmp, 1.f / 3.f);
            radius = fminf(radius / den, 1e16f);
            dec = 2.f;
#pragma unroll
            for (int k = 0; k < 10; k++) jt[k] = t[k];
#pragma unroll
            for (int k = 0; k < 4; k++) gr[k] = t[10 + k];
            cst = cn;
#pragma unroll
            for (int k = 0; k < 4; k++) pose[k] = pn[k];
        } else {
            radius = radius / dec;
            dec *= 2.f;
            // next pass must run at the accepted pose again
            sincosf(pose[3], &sy, &cy);
            tx = pose[0]; ty = pose[1]; tz = pose[2];
        }
    }

    // ---- outputs + GN step (reuses carried jtj/grad) ----
    if (tid == 0) {
        float* __restrict__ out_pose = out + (size_t)b * 4;
        float* __restrict__ out_cost = out + (size_t)4 * B + b;
        float* __restrict__ out_plus = out + (size_t)5 * B + (size_t)b * 4;
#pragma unroll
        for (int k = 0; k < 4; k++) out_pose[k] = pose[k];
        *out_cost = cst;

        float A[4][4], bvec[4], xx[4];
        A[0][0] = jt[0]; A[0][1] = jt[1]; A[0][2] = jt[2]; A[0][3] = jt[3];
        A[1][0] = jt[1]; A[1][1] = jt[4]; A[1][2] = jt[5]; A[1][3] = jt[6];
        A[2][0] = jt[2]; A[2][1] = jt[5]; A[2][2] = jt[7]; A[2][3] = jt[8];
        A[3][0] = jt[3]; A[3][1] = jt[6]; A[3][2] = jt[8]; A[3][3] = jt[9];
#pragma unroll
        for (int i = 0; i < 4; i++) {
            A[i][i] += 1e-5f;          // EPS * eye
            bvec[i] = gr[i];
        }
        solve4f(A, bvec, xx);
#pragma unroll
        for (int k = 0; k < 4; k++)
            out_plus[k] = pose[k] - xx[k];
    }
}

extern "C" void kernel_launch(void* const* d_in, const int* in_sizes, int n_in,
                              void* d_out, int out_size) {
    const float* x3d       = (const float*)d_in[0];
    const float* x2d       = (const float*)d_in[1];
    const float* w2d       = (const float*)d_in[2];
    const float* pose_init = (const float*)d_in[3];
    const float* cam_mats  = (const float*)d_in[4];
    const int B = in_sizes[3] / 4;
    float* out = (float*)d_out;
    lm_kernel<<<B, THREADS>>>(x3d, x2d, w2d, pose_init, cam_mats, out, B);
}

// round 13
// speedup vs baseline: 7.7104x; 1.0418x over previous
#include <cuda_runtime.h>

// LM pose solver: B=4096 batches, N=512 points, DOF=4 (tx,ty,tz,yaw).
// One 32-thread CTA (single warp) per batch; 8 packed f32x2 point-pairs per
// lane. Pinhole-K fast path (exact zeros -> bit-identical to general form).
// This round: rcp.approx replaces ALL divisions in the per-iteration
// bookkeeping (solve pivots/back-sub, trust-region updates), __sinf/__cosf
// replace sincosf, and mcc uses the identity mcc = 0.5*(s'Ds - s.g)
// (exact algebra from (jtj+D)s = -g), shortening the serial chain that
// dominates at 15 warps/SM.

#define NPTS     512
#define NPAIRS_T 256                     // total float2 pairs
#define THREADS  32
#define NPAIRS   (NPAIRS_T / THREADS)    // 8 pairs per lane
#define NUM_ITER 10

typedef unsigned long long u64;

__device__ __forceinline__ u64 pk2(float lo, float hi) {
    u64 r; asm("mov.b64 %0,{%1,%2};" : "=l"(r) : "f"(lo), "f"(hi)); return r;
}
__device__ __forceinline__ u64 pkb(float s) { return pk2(s, s); }
__device__ __forceinline__ void unpk2(u64 a, float& lo, float& hi) {
    asm("mov.b64 {%0,%1},%2;" : "=f"(lo), "=f"(hi) : "l"(a));
}
__device__ __forceinline__ u64 f2fma(u64 a, u64 b, u64 c) {
    u64 d; asm("fma.rn.f32x2 %0,%1,%2,%3;" : "=l"(d) : "l"(a), "l"(b), "l"(c)); return d;
}
__device__ __forceinline__ u64 f2mul(u64 a, u64 b) {
    u64 d; asm("mul.rn.f32x2 %0,%1,%2;" : "=l"(d) : "l"(a), "l"(b)); return d;
}
__device__ __forceinline__ u64 f2add(u64 a, u64 b) {
    u64 d; asm("add.rn.f32x2 %0,%1,%2;" : "=l"(d) : "l"(a), "l"(b)); return d;
}
__device__ __forceinline__ float frcp(float x) {
    float r; asm("rcp.approx.f32 %0, %1;" : "=f"(r) : "f"(x)); return r;
}
// warp butterfly sum (all lanes get total)
__device__ __forceinline__ float wsum(float x) {
#pragma unroll
    for (int o = 16; o > 0; o >>= 1)
        x += __shfl_xor_sync(0xffffffffu, x, o);
    return x;
}

// fp32 Gaussian elimination, no pivoting (A is SPD + LM damping).
// All reciprocals via rcp.approx (error ~1ulp*few, far inside 1e-3 budget).
__device__ __forceinline__ void solve4f(float A[4][4], float bv[4], float x[4]) {
#pragma unroll
    for (int k = 0; k < 4; k++) {
        const float inv = frcp(A[k][k]);
#pragma unroll
        for (int i = 0; i < 4; i++) {
            if (i > k) {
                const float f = A[i][k] * inv;
#pragma unroll
                for (int j = 0; j < 4; j++)
                    if (j >= k) A[i][j] = fmaf(-f, A[k][j], A[i][j]);
                bv[i] = fmaf(-f, bv[k], bv[i]);
            }
        }
    }
#pragma unroll
    for (int k = 3; k >= 0; k--) {
        float s = bv[k];
#pragma unroll
        for (int j = 0; j < 4; j++)
            if (j > k) s = fmaf(-A[k][j], x[j], s);
        x[k] = s * frcp(A[k][k]);
    }
}

__global__ void __launch_bounds__(THREADS, 15) lm_kernel(
    const float* __restrict__ x3d,
    const float* __restrict__ x2d,
    const float* __restrict__ w2d,
    const float* __restrict__ pose_init,
    const float* __restrict__ cam,
    float* __restrict__ out,   // [4B pose | B cost | 4B pose_plus]
    int B)
{
    // pair-packed layout: one pair (2 points) = sA.xyzw=(X0,X1,Y0,Y1),
    // sB=(Z0,Z1,WU0,WU1), sC=(WV0,WV1,NUW0,NUW1), sD=(NVW0,NVW1)
    __shared__ float4 sA[NPAIRS_T], sB[NPAIRS_T], sC[NPAIRS_T];
    __shared__ float2 sD[NPAIRS_T];

    const int b   = blockIdx.x;
    const int tid = threadIdx.x;

    // ---- stage point data (one-time) ----
    const float*  __restrict__ xb = x3d + (size_t)b * NPTS * 3;
    const float2* __restrict__ ub = (const float2*)(x2d + (size_t)b * NPTS * 2);
    const float2* __restrict__ wb = (const float2*)(w2d + (size_t)b * NPTS * 2);
    for (int j = tid; j < NPAIRS_T; j += THREADS) {
        const float X0 = xb[6*j+0], Y0 = xb[6*j+1], Z0 = xb[6*j+2];
        const float X1 = xb[6*j+3], Y1 = xb[6*j+4], Z1 = xb[6*j+5];
        const float2 u0 = ub[2*j], u1 = ub[2*j+1];
        const float2 w0 = wb[2*j], w1 = wb[2*j+1];
        sA[j] = make_float4(X0, X1, Y0, Y1);
        sB[j] = make_float4(Z0, Z1, w0.x, w1.x);
        sC[j] = make_float4(w0.y, w1.y, -(u0.x*w0.x), -(u1.x*w1.x));
        sD[j] = make_float2(-(u0.y*w0.y), -(u1.y*w1.y));
    }

    float Kr[9];
#pragma unroll
    for (int k = 0; k < 9; k++) Kr[k] = cam[(size_t)b * 9 + k];
    // Pinhole check: with exact zeros the specialized math is BIT-IDENTICAL
    // to the general formula (fmaf(x,0,y)==y exactly).
    const bool pin = (Kr[1] == 0.f) && (Kr[3] == 0.f) && (Kr[6] == 0.f) &&
                     (Kr[7] == 0.f) && (Kr[8] == 1.f);

    float pose[4];
#pragma unroll
    for (int k = 0; k < 4; k++) pose[k] = pose_init[b * 4 + k];
    float jt[10], gr[4];
    float cst = 0.f, radius = 30.0f, dec = 2.0f;

    float cy = __cosf(pose[3]);
    float sy = __sinf(pose[3]);
    float tx = pose[0], ty = pose[1], tz = pose[2];

    __syncwarp();   // staging visible warp-wide

    float t[15];

    // One fused residual+jacobian reduction pass at (tx,ty,tz,cy,sy).
    // On exit every lane holds the batch-wide sums in t[0..14]
    // (t[14]=2*cost is reduced FIRST to shorten the accept-decision path).
    auto do_pass = [&]() {
        if (pin) {
            const float fx = Kr[0], cx = Kr[2], fy = Kr[4], cyk = Kr[5];
            u64 A0 = 0, A2 = 0, A3 = 0, A4 = 0, A5 = 0, A6 = 0, A7 = 0,
                A8 = 0, A9 = 0, A10 = 0, A11 = 0, A12 = 0, A13 = 0, A14 = 0;
            const u64 TX = pkb(tx), TY = pkb(ty), TZ = pkb(tz), nTZ = pkb(-tz);
            const u64 CYr = pkb(cy), SYr = pkb(sy), nSY = pkb(-sy);
            const u64 FX = pkb(fx), CX = pkb(cx), FY = pkb(fy), CYK = pkb(cyk);
            const u64 M1 = pkb(-1.0f);
#pragma unroll
            for (int p = 0; p < NPAIRS; p++) {
                const int j = tid + p * THREADS;
                const float4 a4 = sA[j];
                const float4 b4 = sB[j];
                const float4 c4 = sC[j];
                const float2 d2 = sD[j];
                const u64 Px = pk2(a4.x, a4.y), Py = pk2(a4.z, a4.w);
                const u64 Pz = pk2(b4.x, b4.y), WU = pk2(b4.z, b4.w);
                const u64 WV = pk2(c4.x, c4.y), NUW = pk2(c4.z, c4.w);
                const u64 NVW = pk2(d2.x, d2.y);
                const u64 p0 = f2fma(CYr, Px, f2fma(SYr, Pz, TX));
                const u64 p1 = f2add(Py, TY);
                const u64 p2 = f2fma(nSY, Px, f2fma(CYr, Pz, TZ));
                const u64 av = f2add(p2, nTZ);          //  -s*X + c*Z
                const u64 bv = f2fma(p0, M1, TX);       // -(c*X + s*Z)
                const u64 ph0 = f2fma(FX, p0, f2mul(CX, p2));
                const u64 ph1 = f2fma(FY, p1, f2mul(CYK, p2));
                float z0, z1; unpk2(p2, z0, z1);        // ph2 == p2 (K8==1)
                const float i0 = frcp(fmaxf(z0, 0.1f));
                const float i1 = frcp(fmaxf(z1, 0.1f));
                const float g0 = (z0 > 0.1f) ? 1.f : ((z0 == 0.1f) ? 0.5f : 0.f);
                const float g1 = (z1 > 0.1f) ? 1.f : ((z1 == 0.1f) ? 0.5f : 0.f);
                const u64 invz = pk2(i0, i1);
                const u64 gz   = pk2(g0, g1);
                const u64 u  = f2mul(ph0, invz);
                const u64 v  = f2mul(ph1, invz);
                const u64 ru = f2fma(u, WU, NUW);       // u*wu - x2d_u*wu
                const u64 rv = f2fma(v, WV, NVW);
                const u64 su = f2mul(WU, invz);
                const u64 sv = f2mul(WV, invz);
                const u64 ug = f2mul(u, gz);
                const u64 vg = f2mul(v, gz);
                const u64 Ju0 = f2mul(FX, su);
                const u64 Jv1 = f2mul(FY, sv);
                const u64 Ju2 = f2mul(f2fma(ug, M1, CX), su);
                const u64 Jv2 = f2mul(f2fma(vg, M1, CYK), sv);
                const u64 Ju3 = f2fma(Ju0, av, f2mul(Ju2, bv));
                const u64 Jv3 = f2mul(Jv2, bv);
                A0  = f2fma(Ju0, Ju0, A0);
                A2  = f2fma(Ju0, Ju2, A2);
                A3  = f2fma(Ju0, Ju3, A3);
                A4  = f2fma(Jv1, Jv1, A4);
                A5  = f2fma(Jv1, Jv2, A5);
                A6  = f2fma(Jv1, Jv3, A6);
                A7  = f2fma(Ju2, Ju2, f2fma(Jv2, Jv2, A7));
                A8  = f2fma(Ju2, Ju3, f2fma(Jv2, Jv3, A8));
                A9  = f2fma(Ju3, Ju3, f2fma(Jv3, Jv3, A9));
                A10 = f2fma(Ju0, ru, A10);
                A11 = f2fma(Jv1, rv, A11);
                A12 = f2fma(Ju2, ru, f2fma(Jv2, rv, A12));
                A13 = f2fma(Ju3, ru, f2fma(Jv3, rv, A13));
                A14 = f2fma(ru, ru, f2fma(rv, rv, A14));
            }
            float l, h;
            // cost first: shortest path to the accept decision
            unpk2(A14, l, h); t[14] = wsum(l + h);
            t[1] = 0.f;                                  // Ju1==Jv0==0 exactly
            unpk2(A0, l, h);  t[0]  = wsum(l + h);
            unpk2(A2, l, h);  t[2]  = wsum(l + h);
            unpk2(A3, l, h);  t[3]  = wsum(l + h);
            unpk2(A4, l, h);  t[4]  = wsum(l + h);
            unpk2(A5, l, h);  t[5]  = wsum(l + h);
            unpk2(A6, l, h);  t[6]  = wsum(l + h);
            unpk2(A7, l, h);  t[7]  = wsum(l + h);
            unpk2(A8, l, h);  t[8]  = wsum(l + h);
            unpk2(A9, l, h);  t[9]  = wsum(l + h);
            unpk2(A10, l, h); t[10] = wsum(l + h);
            unpk2(A11, l, h); t[11] = wsum(l + h);
            unpk2(A12, l, h); t[12] = wsum(l + h);
            unpk2(A13, l, h); t[13] = wsum(l + h);
        } else {
            // general-K fallback (not taken for this dataset)
            float a[15];
#pragma unroll
            for (int k = 0; k < 15; k++) a[k] = 0.f;
#pragma unroll 1
            for (int p = 0; p < NPAIRS; p++) {
                const int j = tid + p * THREADS;
                const float4 a4 = sA[j];
                const float4 b4 = sB[j];
                const float4 c4 = sC[j];
                const float2 d2 = sD[j];
#pragma unroll
                for (int hlf = 0; hlf < 2; hlf++) {
                    const float X = hlf ? a4.y : a4.x;
                    const float Y = hlf ? a4.w : a4.z;
                    const float Z = hlf ? b4.y : b4.x;
                    const float wu = hlf ? b4.w : b4.z;
                    const float wv = hlf ? c4.y : c4.x;
                    const float nuw = hlf ? c4.w : c4.z;
                    const float nvw = hlf ? d2.y : d2.x;
                    const float p0 = fmaf(cy, X, fmaf(sy, Z, tx));
                    const float p1 = Y + ty;
                    const float p2 = fmaf(-sy, X, fmaf(cy, Z, tz));
                    const float avv = p2 - tz;
                    const float bvv = tx - p0;
                    const float ph0 = fmaf(Kr[0], p0, fmaf(Kr[1], p1, Kr[2] * p2));
                    const float ph1 = fmaf(Kr[3], p0, fmaf(Kr[4], p1, Kr[5] * p2));
                    const float ph2 = fmaf(Kr[6], p0, fmaf(Kr[7], p1, Kr[8] * p2));
                    const float zc  = fmaxf(ph2, 0.1f);
                    const float gz  = (ph2 > 0.1f) ? 1.f : ((ph2 == 0.1f) ? 0.5f : 0.f);
                    const float invz = 1.0f / zc;
                    const float u = ph0 * invz;
                    const float v = ph1 * invz;
                    const float ru = fmaf(u, wu, nuw);
                    const float rv = fmaf(v, wv, nvw);
                    const float d0y = fmaf(Kr[0], avv, Kr[2] * bvv);
                    const float d1y = fmaf(Kr[3], avv, Kr[5] * bvv);
                    const float d2y = fmaf(Kr[6], avv, Kr[8] * bvv);
                    const float su_ = wu * invz;
                    const float sv_ = wv * invz;
                    const float ug = u * gz;
                    const float vg = v * gz;
                    const float Ju0 = fmaf(-ug, Kr[6], Kr[0]) * su_;
                    const float Ju1 = fmaf(-ug, Kr[7], Kr[1]) * su_;
                    const float Ju2 = fmaf(-ug, Kr[8], Kr[2]) * su_;
                    const float Ju3 = fmaf(-ug, d2y,  d0y ) * su_;
                    const float Jv0 = fmaf(-vg, Kr[6], Kr[3]) * sv_;
                    const float Jv1 = fmaf(-vg, Kr[7], Kr[4]) * sv_;
                    const float Jv2 = fmaf(-vg, Kr[8], Kr[5]) * sv_;
                    const float Jv3 = fmaf(-vg, d2y,  d1y ) * sv_;
                    a[0] = fmaf(Ju0, Ju0, fmaf(Jv0, Jv0, a[0]));
                    a[1] = fmaf(Ju0, Ju1, fmaf(Jv0, Jv1, a[1]));
                    a[2] = fmaf(Ju0, Ju2, fmaf(Jv0, Jv2, a[2]));
                    a[3] = fmaf(Ju0, Ju3, fmaf(Jv0, Jv3, a[3]));
                    a[4] = fmaf(Ju1, Ju1, fmaf(Jv1, Jv1, a[4]));
                    a[5] = fmaf(Ju1, Ju2, fmaf(Jv1, Jv2, a[5]));
                    a[6] = fmaf(Ju1, Ju3, fmaf(Jv1, Jv3, a[6]));
                    a[7] = fmaf(Ju2, Ju2, fmaf(Jv2, Jv2, a[7]));
                    a[8] = fmaf(Ju2, Ju3, fmaf(Jv2, Jv3, a[8]));
                    a[9] = fmaf(Ju3, Ju3, fmaf(Jv3, Jv3, a[9]));
                    a[10] = fmaf(Ju0, ru, fmaf(Jv0, rv, a[10]));
                    a[11] = fmaf(Ju1, ru, fmaf(Jv1, rv, a[11]));
                    a[12] = fmaf(Ju2, ru, fmaf(Jv2, rv, a[12]));
                    a[13] = fmaf(Ju3, ru, fmaf(Jv3, rv, a[13]));
                    a[14] = fmaf(ru, ru, fmaf(rv, rv, a[14]));
                }
            }
#pragma unroll
            for (int k = 0; k < 15; k++) t[k] = wsum(a[k]);
        }
    };

    // ---- initial pass at pose_init ----
    do_pass();
#pragma unroll
    for (int k = 0; k < 10; k++) jt[k] = t[k];
#pragma unroll
    for (int k = 0; k < 4; k++) gr[k] = t[10 + k];
    cst = 0.5f * t[14];

    float stepv[4], pn[4], dval[4];

    // ---- LM iterations ----
    for (int it = 0; it < NUM_ITER; it++) {
        {
            float A[4][4], bvec[4], xx[4];
            A[0][0] = jt[0]; A[0][1] = jt[1]; A[0][2] = jt[2]; A[0][3] = jt[3];
            A[1][0] = jt[1]; A[1][1] = jt[4]; A[1][2] = jt[5]; A[1][3] = jt[6];
            A[2][0] = jt[2]; A[2][1] = jt[5]; A[2][2] = jt[7]; A[2][3] = jt[8];
            A[3][0] = jt[3]; A[3][1] = jt[6]; A[3][2] = jt[8]; A[3][3] = jt[9];
            const float dg[4] = {jt[0], jt[4], jt[7], jt[9]};
            const float irad = frcp(radius);
#pragma unroll
            for (int i = 0; i < 4; i++) {
                const float d = fminf(fmaxf(dg[i], 1e-6f), 1e32f);
                dval[i] = d * irad;           // LM damping added to diagonal
                A[i][i] += dval[i];
                bvec[i] = gr[i];
            }
            solve4f(A, bvec, xx);
#pragma unroll
            for (int i = 0; i < 4; i++) {
                stepv[i] = -xx[i];
                pn[i] = pose[i] + stepv[i];
            }
        }
        cy = __cosf(pn[3]);
        sy = __sinf(pn[3]);
        tx = pn[0]; ty = pn[1]; tz = pn[2];

        do_pass();

        const float cn = 0.5f * t[14];
        // mcc = -s.(g + 0.5*jtj*s) == 0.5*(s'Ds - s.g)  [(jtj+D)s = -g]
        float sDs = 0.f, sg = 0.f;
#pragma unroll
        for (int i = 0; i < 4; i++) {
            sDs = fmaf(dval[i] * stepv[i], stepv[i], sDs);
            sg  = fmaf(stepv[i], gr[i], sg);
        }
        const float mcc = 0.5f * (sDs - sg);
        const float rel = (cst - cn) * frcp(mcc);
        const bool succ = (rel >= 1e-3f) && (mcc > 0.0f);
        if (succ) {
            const float tmp = 2.f * rel - 1.f;
            const float den = fmaxf(1.f - tmp * tmp * tmp, 1.f / 3.f);
            radius = fminf(radius * frcp(den), 1e16f);
            dec = 2.f;
#pragma unroll
            for (int k = 0; k < 10; k++) jt[k] = t[k];
#pragma unroll
            for (int k = 0; k < 4; k++) gr[k] = t[10 + k];
            cst = cn;
#pragma unroll
            for (int k = 0; k < 4; k++) pose[k] = pn[k];
        } else {
            radius = radius * frcp(dec);   // dec = 2^k: frcp exact
            dec *= 2.f;
            // next pass must run at the accepted pose again
            cy = __cosf(pose[3]);
            sy = __sinf(pose[3]);
            tx = pose[0]; ty = pose[1]; tz = pose[2];
        }
    }

    // ---- outputs + GN step (reuses carried jtj/grad) ----
    if (tid == 0) {
        float* __restrict__ out_pose = out + (size_t)b * 4;
        float* __restrict__ out_cost = out + (size_t)4 * B + b;
        float* __restrict__ out_plus = out + (size_t)5 * B + (size_t)b * 4;
#pragma unroll
        for (int k = 0; k < 4; k++) out_pose[k] = pose[k];
        *out_cost = cst;

        float A[4][4], bvec[4], xx[4];
        A[0][0] = jt[0]; A[0][1] = jt[1]; A[0][2] = jt[2]; A[0][3] = jt[3];
        A[1][0] = jt[1]; A[1][1] = jt[4]; A[1][2] = jt[5]; A[1][3] = jt[6];
        A[2][0] = jt[2]; A[2][1] = jt[5]; A[2][2] = jt[7]; A[2][3] = jt[8];
        A[3][0] = jt[3]; A[3][1] = jt[6]; A[3][2] = jt[8]; A[3][3] = jt[9];
#pragma unroll
        for (int i = 0; i < 4; i++) {
            A[i][i] += 1e-5f;          // EPS * eye
            bvec[i] = gr[i];
        }
        solve4f(A, bvec, xx);
#pragma unroll
        for (int k = 0; k < 4; k++)
            out_plus[k] = pose[k] - xx[k];
    }
}

extern "C" void kernel_launch(void* const* d_in, const int* in_sizes, int n_in,
                              void* d_out, int out_size) {
    const float* x3d       = (const float*)d_in[0];
    const float* x2d       = (const float*)d_in[1];
    const float* w2d       = (const float*)d_in[2];
    const float* pose_init = (const float*)d_in[3];
    const float* cam_mats  = (const float*)d_in[4];
    const int B = in_sizes[3] / 4;
    float* out = (float*)d_out;
    lm_kernel<<<B, THREADS>>>(x3d, x2d, w2d, pose_init, cam_mats, out, B);
}